// round 2
// baseline (speedup 1.0000x reference)
#include <cuda_runtime.h>
#include <cstdint>

#define NS   32768
#define NA   2048
#define ASZ  1024
#define KSP  64
#define NB   4
#define NEG_INF (-3.4e38f)
#define CAND_MAX 65536
#define NTILES   4096          // 16 atom-blocks x 256 time-blocks per batch

// ---------------- small static scratch (~2.3 MB total) ----------------
__device__ float    g_tilemax[NB * NTILES];
__device__ float    g_thresh[NB];
__device__ unsigned g_work[NB][NTILES];
__device__ unsigned g_work_cnt[NB];
__device__ float    g_cand_val[NB][CAND_MAX];
__device__ unsigned g_cand_idx[NB][CAND_MAX];
__device__ unsigned g_cand_cnt[NB];
__device__ float    g_topv[NB * KSP];
__device__ unsigned g_topi[NB * KSP];

__global__ void init_kernel() {
    int i = blockIdx.x * blockDim.x + threadIdx.x;
    if (i < NB) { g_cand_cnt[i] = 0u; g_work_cnt[i] = 0u; }
}

// ---------------- shared GEMM core: one 128(atoms) x 128(times) x 1024 tile ----------------
// acc[i][j] = sum_k orig[b, t0 + tx*8 + j + k - 512] * atoms[a0 + ty*8 + i, k]
__device__ __forceinline__ void tile_gemm(
    const float* __restrict__ ob, const float* __restrict__ atoms,
    int a0, int t0, int tid, float acc[8][8],
    float (*As)[132], float* Bs)
{
    const int tx = tid & 15, ty = tid >> 4;
    const int kload = tid & 15, sload = tid >> 4;
#pragma unroll
    for (int i = 0; i < 8; i++)
#pragma unroll
        for (int j = 0; j < 8; j++) acc[i][j] = 0.f;

    for (int kk = 0; kk < ASZ; kk += 16) {
#pragma unroll
        for (int i = 0; i < 8; i++) {
            int a = (i << 4) + sload;
            As[kload][a] = atoms[(size_t)(a0 + a) * ASZ + kk + kload];
        }
        if (tid < 160) {
            int src = t0 + kk - 512 + tid;
            Bs[tid] = (src >= 0 && src < NS) ? ob[src] : 0.f;
        }
        __syncthreads();

        float br[24];
#pragma unroll
        for (int q = 0; q < 6; q++) {
            float4 v = *(const float4*)&Bs[(tx << 3) + (q << 2)];
            br[q * 4 + 0] = v.x; br[q * 4 + 1] = v.y;
            br[q * 4 + 2] = v.z; br[q * 4 + 3] = v.w;
        }
#pragma unroll
        for (int k = 0; k < 16; k++) {
            float4 a01 = *(const float4*)&As[k][(ty << 3)];
            float4 a23 = *(const float4*)&As[k][(ty << 3) + 4];
            float ar[8] = {a01.x, a01.y, a01.z, a01.w, a23.x, a23.y, a23.z, a23.w};
#pragma unroll
            for (int i = 0; i < 8; i++)
#pragma unroll
                for (int j = 0; j < 8; j++)
                    acc[i][j] = fmaf(ar[i], br[k + j], acc[i][j]);
        }
        __syncthreads();
    }
}

// ---------------- pass 1: correlation + per-tile max only (no bulk stores) ----------------
__global__ __launch_bounds__(256, 2)
void corr_max_kernel(const float* __restrict__ orig, const float* __restrict__ atoms) {
    __shared__ float As[16][132];
    __shared__ float Bs[160];
    __shared__ float wmax[8];
    const int b = blockIdx.z, a0 = blockIdx.y << 7, t0 = blockIdx.x << 7;
    const int tid = threadIdx.x;

    float acc[8][8];
    tile_gemm(orig + (size_t)b * NS, atoms, a0, t0, tid, acc, As, Bs);

    float m = NEG_INF;
#pragma unroll
    for (int i = 0; i < 8; i++)
#pragma unroll
        for (int j = 0; j < 8; j++) m = fmaxf(m, acc[i][j]);
#pragma unroll
    for (int o = 16; o > 0; o >>= 1) m = fmaxf(m, __shfl_xor_sync(0xffffffffu, m, o));
    if ((tid & 31) == 0) wmax[tid >> 5] = m;
    __syncthreads();
    if (tid == 0) {
        float mm = wmax[0];
#pragma unroll
        for (int w = 1; w < 8; w++) mm = fmaxf(mm, wmax[w]);
        g_tilemax[b * NTILES + blockIdx.y * 256 + blockIdx.x] = mm;
    }
}

// ---------------- threshold: 64th-largest tile max per batch ----------------
__global__ void thresh_kernel() {
    __shared__ float sv[NTILES];
    __shared__ float rv[256];
    __shared__ int   ri[256];
    const int b = blockIdx.x, tid = threadIdx.x;
    for (int i = tid; i < NTILES; i += 256) sv[i] = g_tilemax[b * NTILES + i];
    __syncthreads();
    for (int it = 0; it < KSP; it++) {
        float best = NEG_INF; int bi = 0;
        for (int i = tid; i < NTILES; i += 256)
            if (sv[i] > best) { best = sv[i]; bi = i; }
        rv[tid] = best; ri[tid] = bi;
        __syncthreads();
        for (int s = 128; s > 0; s >>= 1) {
            if (tid < s && rv[tid + s] > rv[tid]) { rv[tid] = rv[tid + s]; ri[tid] = ri[tid + s]; }
            __syncthreads();
        }
        if (tid == 0) {
            if (it == KSP - 1) g_thresh[b] = rv[0];
            sv[ri[0]] = NEG_INF;
        }
        __syncthreads();
    }
}

// ---------------- build hot-tile work list ----------------
__global__ void worklist_kernel() {
    const int b = blockIdx.x;
    const float tau = g_thresh[b];
    for (int i = threadIdx.x; i < NTILES; i += blockDim.x) {
        if (g_tilemax[b * NTILES + i] >= tau) {
            unsigned p = atomicAdd(&g_work_cnt[b], 1u);
            g_work[b][p] = (unsigned)i;
        }
    }
}

// ---------------- pass 2: recompute hot tiles, compact candidates >= tau ----------------
__global__ __launch_bounds__(256, 2)
void recompute_kernel(const float* __restrict__ orig, const float* __restrict__ atoms) {
    __shared__ float As[16][132];
    __shared__ float Bs[160];
    const int b = blockIdx.y;
    const float tau = g_thresh[b];
    const unsigned cnt = g_work_cnt[b];
    const int tid = threadIdx.x;
    const int tx = tid & 15, ty = tid >> 4;

    for (unsigned w = blockIdx.x; w < cnt; w += gridDim.x) {
        unsigned tile = g_work[b][w];
        int a0 = (int)(tile >> 8) << 7;          // tile = by*256 + bx
        int t0 = (int)(tile & 255u) << 7;
        float acc[8][8];
        tile_gemm(orig + (size_t)b * NS, atoms, a0, t0, tid, acc, As, Bs);

#pragma unroll
        for (int i = 0; i < 8; i++) {
            int a = a0 + (ty << 3) + i;
#pragma unroll
            for (int j = 0; j < 8; j++) {
                if (acc[i][j] >= tau) {
                    unsigned pos = atomicAdd(&g_cand_cnt[b], 1u);
                    if (pos < CAND_MAX) {
                        g_cand_val[b][pos] = acc[i][j];
                        g_cand_idx[b][pos] = (unsigned)a * (unsigned)NS + (unsigned)(t0 + (tx << 3) + j);
                    }
                }
            }
        }
        __syncthreads();
    }
}

// ---------------- exact top-64 among candidates ----------------
__global__ void select_kernel() {
    __shared__ float rv[256];
    __shared__ int   ri[256];
    const int b = blockIdx.x, tid = threadIdx.x;
    unsigned n = g_cand_cnt[b];
    if (n > CAND_MAX) n = CAND_MAX;
    for (int it = 0; it < KSP; it++) {
        float best = NEG_INF; int bi = 0;
        for (unsigned i = tid; i < n; i += 256) {
            float v = g_cand_val[b][i];
            if (v > best) { best = v; bi = (int)i; }
        }
        rv[tid] = best; ri[tid] = bi;
        __syncthreads();
        for (int s = 128; s > 0; s >>= 1) {
            if (tid < s && rv[tid + s] > rv[tid]) { rv[tid] = rv[tid + s]; ri[tid] = ri[tid + s]; }
            __syncthreads();
        }
        if (tid == 0) {
            g_topv[b * KSP + it] = rv[0];
            g_topi[b * KSP + it] = g_cand_idx[b][ri[0]];
            g_cand_val[b][ri[0]] = NEG_INF;
        }
        __syncthreads();
    }
}

// ---------------- reconstruction: deterministic gather ----------------
__global__ void output_kernel(const float* __restrict__ atoms, float* __restrict__ out) {
    __shared__ float sv[KSP];
    __shared__ int   sa[KSP];
    __shared__ int   st[KSP];
    const int b = blockIdx.y, tid = threadIdx.x;
    if (tid < KSP) {
        sv[tid] = g_topv[b * KSP + tid];
        unsigned idx = g_topi[b * KSP + tid];
        sa[tid] = (int)(idx / (unsigned)NS);
        st[tid] = (int)(idx % (unsigned)NS);
    }
    __syncthreads();
    const int p = blockIdx.x * blockDim.x + tid;
    float acc = 0.f;
#pragma unroll 8
    for (int j = 0; j < KSP; j++) {
        int o = p - st[j];
        if ((unsigned)o < (unsigned)ASZ) acc += atoms[(size_t)sa[j] * ASZ + o] * sv[j];
    }
    out[(size_t)b * NS + p] = acc;
}

// ---------------- launch ----------------
extern "C" void kernel_launch(void* const* d_in, const int* in_sizes, int n_in,
                              void* d_out, int out_size) {
    const float* orig  = (const float*)d_in[0];
    const float* atoms = (const float*)d_in[1];
    if (n_in >= 2 && in_sizes[0] == NA * ASZ) {   // defensive operand-order check
        const float* t = orig; orig = atoms; atoms = t;
    }
    float* out = (float*)d_out;

    init_kernel<<<1, 32>>>();
    corr_max_kernel<<<dim3(256, 16, NB), 256>>>(orig, atoms);
    thresh_kernel<<<NB, 256>>>();
    worklist_kernel<<<NB, 256>>>();
    recompute_kernel<<<dim3(256, NB), 256>>>(orig, atoms);
    select_kernel<<<NB, 256>>>();
    output_kernel<<<dim3(NS / 256, NB), 256>>>(atoms, out);
}

// round 3
// speedup vs baseline: 1.1128x; 1.1128x over previous
#include <cuda_runtime.h>
#include <cstdint>

#define NS   32768
#define NA   2048
#define ASZ  1024
#define KSP  64
#define NB   4
#define NEG_INF (-3.4e38f)
#define CAND_MAX 65536
#define NTILES   4096          // 16 atom-blocks x 256 time-blocks per batch

typedef unsigned long long ull;

// ---------------- small static scratch (~2.3 MB total) ----------------
__device__ float    g_tilemax[NB * NTILES];
__device__ float    g_thresh[NB];
__device__ unsigned g_work[NB][NTILES];
__device__ unsigned g_work_cnt[NB];
__device__ float    g_cand_val[NB][CAND_MAX];
__device__ unsigned g_cand_idx[NB][CAND_MAX];
__device__ unsigned g_cand_cnt[NB];
__device__ float    g_topv[NB * KSP];
__device__ unsigned g_topi[NB * KSP];

__global__ void init_kernel() {
    int i = blockIdx.x * blockDim.x + threadIdx.x;
    if (i < NB) { g_cand_cnt[i] = 0u; g_work_cnt[i] = 0u; }
}

__device__ __forceinline__ float f32x2_lo(ull v) { return __uint_as_float((unsigned)(v & 0xffffffffull)); }
__device__ __forceinline__ float f32x2_hi(ull v) { return __uint_as_float((unsigned)(v >> 32)); }

// ---------------- shared GEMM core: one 128(atoms) x 128(times) x 1024 tile ----------------
// Packed f32x2: accumulator pairs over the ATOM dimension.
// acc2[i2][j] holds { corr(atom 2*i2+0, time j), corr(atom 2*i2+1, time j) } for this
// thread's sub-tile: atoms a0 + (ty<<3) + {0..7}, times t0 + (tx<<3) + {0..7}.
__device__ __forceinline__ void tile_gemm(
    const float* __restrict__ ob, const float* __restrict__ atoms,
    int a0, int t0, int tid, ull acc2[4][8],
    float (*As)[132], float* Bs)
{
    const int tx = tid & 15, ty = tid >> 4;
    const int kload = tid & 15, sload = tid >> 4;
#pragma unroll
    for (int i2 = 0; i2 < 4; i2++)
#pragma unroll
        for (int j = 0; j < 8; j++) acc2[i2][j] = 0ull;

    for (int kk = 0; kk < ASZ; kk += 16) {
        // load 128x16 atom chunk, coalesced along k, transposed into As[k][a]
#pragma unroll
        for (int i = 0; i < 8; i++) {
            int a = (i << 4) + sload;
            As[kload][a] = atoms[(size_t)(a0 + a) * ASZ + kk + kload];
        }
        // 1-D signal slice with zero padding (143 needed, load 160)
        if (tid < 160) {
            int src = t0 + kk - 512 + tid;
            Bs[tid] = (src >= 0 && src < NS) ? ob[src] : 0.f;
        }
        __syncthreads();

        // B fragment: 24 floats cover k+j in [0,23] for this thread's 8 times
        unsigned br[24];
#pragma unroll
        for (int q = 0; q < 6; q++) {
            float4 v = *(const float4*)&Bs[(tx << 3) + (q << 2)];
            br[q * 4 + 0] = __float_as_uint(v.x); br[q * 4 + 1] = __float_as_uint(v.y);
            br[q * 4 + 2] = __float_as_uint(v.z); br[q * 4 + 3] = __float_as_uint(v.w);
        }
#pragma unroll
        for (int k = 0; k < 16; k++) {
            // atom pairs: 4 x 8-byte loads (even float offsets -> 8B aligned)
            ull ar2[4];
#pragma unroll
            for (int i2 = 0; i2 < 4; i2++)
                ar2[i2] = *(const ull*)&As[k][(ty << 3) + (i2 << 1)];
#pragma unroll
            for (int j = 0; j < 8; j++) {
                ull bb;
                asm("mov.b64 %0, {%1, %1};" : "=l"(bb) : "r"(br[k + j]));
#pragma unroll
                for (int i2 = 0; i2 < 4; i2++)
                    asm("fma.rn.f32x2 %0, %1, %2, %0;"
                        : "+l"(acc2[i2][j]) : "l"(ar2[i2]), "l"(bb));
            }
        }
        __syncthreads();
    }
}

// ---------------- pass 1: correlation + per-tile max only (no bulk stores) ----------------
__global__ __launch_bounds__(256, 2)
void corr_max_kernel(const float* __restrict__ orig, const float* __restrict__ atoms) {
    __shared__ float As[16][132];
    __shared__ float Bs[160];
    __shared__ float wmax[8];
    const int b = blockIdx.z, a0 = blockIdx.y << 7, t0 = blockIdx.x << 7;
    const int tid = threadIdx.x;

    ull acc2[4][8];
    tile_gemm(orig + (size_t)b * NS, atoms, a0, t0, tid, acc2, As, Bs);

    float m = NEG_INF;
#pragma unroll
    for (int i2 = 0; i2 < 4; i2++)
#pragma unroll
        for (int j = 0; j < 8; j++) {
            m = fmaxf(m, f32x2_lo(acc2[i2][j]));
            m = fmaxf(m, f32x2_hi(acc2[i2][j]));
        }
#pragma unroll
    for (int o = 16; o > 0; o >>= 1) m = fmaxf(m, __shfl_xor_sync(0xffffffffu, m, o));
    if ((tid & 31) == 0) wmax[tid >> 5] = m;
    __syncthreads();
    if (tid == 0) {
        float mm = wmax[0];
#pragma unroll
        for (int w = 1; w < 8; w++) mm = fmaxf(mm, wmax[w]);
        g_tilemax[b * NTILES + blockIdx.y * 256 + blockIdx.x] = mm;
    }
}

// ---------------- threshold: 64th-largest tile max per batch ----------------
// Guarantees: count(x >= tau) >= 64, every global top-64 element >= tau, and
// no tile with max < tau can contain a top-64 element.
__global__ void thresh_kernel() {
    __shared__ float sv[NTILES];
    __shared__ float rv[256];
    __shared__ int   ri[256];
    const int b = blockIdx.x, tid = threadIdx.x;
    for (int i = tid; i < NTILES; i += 256) sv[i] = g_tilemax[b * NTILES + i];
    __syncthreads();
    for (int it = 0; it < KSP; it++) {
        float best = NEG_INF; int bi = 0;
        for (int i = tid; i < NTILES; i += 256)
            if (sv[i] > best) { best = sv[i]; bi = i; }
        rv[tid] = best; ri[tid] = bi;
        __syncthreads();
        for (int s = 128; s > 0; s >>= 1) {
            if (tid < s && rv[tid + s] > rv[tid]) { rv[tid] = rv[tid + s]; ri[tid] = ri[tid + s]; }
            __syncthreads();
        }
        if (tid == 0) {
            if (it == KSP - 1) g_thresh[b] = rv[0];
            sv[ri[0]] = NEG_INF;
        }
        __syncthreads();
    }
}

// ---------------- build hot-tile work list ----------------
__global__ void worklist_kernel() {
    const int b = blockIdx.x;
    const float tau = g_thresh[b];
    for (int i = threadIdx.x; i < NTILES; i += blockDim.x) {
        if (g_tilemax[b * NTILES + i] >= tau) {
            unsigned p = atomicAdd(&g_work_cnt[b], 1u);
            g_work[b][p] = (unsigned)i;
        }
    }
}

// ---------------- pass 2: recompute hot tiles, compact candidates >= tau ----------------
__global__ __launch_bounds__(256, 2)
void recompute_kernel(const float* __restrict__ orig, const float* __restrict__ atoms) {
    __shared__ float As[16][132];
    __shared__ float Bs[160];
    const int b = blockIdx.y;
    const float tau = g_thresh[b];
    const unsigned cnt = g_work_cnt[b];
    const int tid = threadIdx.x;
    const int tx = tid & 15, ty = tid >> 4;

    for (unsigned w = blockIdx.x; w < cnt; w += gridDim.x) {
        unsigned tile = g_work[b][w];
        int a0 = (int)(tile >> 8) << 7;          // tile = by*256 + bx
        int t0 = (int)(tile & 255u) << 7;
        ull acc2[4][8];
        tile_gemm(orig + (size_t)b * NS, atoms, a0, t0, tid, acc2, As, Bs);

#pragma unroll
        for (int i2 = 0; i2 < 4; i2++) {
#pragma unroll
            for (int j = 0; j < 8; j++) {
                float vlo = f32x2_lo(acc2[i2][j]);
                float vhi = f32x2_hi(acc2[i2][j]);
                int abase = a0 + (ty << 3) + (i2 << 1);
                int t = t0 + (tx << 3) + j;
                if (vlo >= tau) {
                    unsigned pos = atomicAdd(&g_cand_cnt[b], 1u);
                    if (pos < CAND_MAX) {
                        g_cand_val[b][pos] = vlo;
                        g_cand_idx[b][pos] = (unsigned)abase * (unsigned)NS + (unsigned)t;
                    }
                }
                if (vhi >= tau) {
                    unsigned pos = atomicAdd(&g_cand_cnt[b], 1u);
                    if (pos < CAND_MAX) {
                        g_cand_val[b][pos] = vhi;
                        g_cand_idx[b][pos] = (unsigned)(abase + 1) * (unsigned)NS + (unsigned)t;
                    }
                }
            }
        }
        __syncthreads();
    }
}

// ---------------- exact top-64 among candidates ----------------
__global__ void select_kernel() {
    __shared__ float rv[256];
    __shared__ int   ri[256];
    const int b = blockIdx.x, tid = threadIdx.x;
    unsigned n = g_cand_cnt[b];
    if (n > CAND_MAX) n = CAND_MAX;
    for (int it = 0; it < KSP; it++) {
        float best = NEG_INF; int bi = 0;
        for (unsigned i = tid; i < n; i += 256) {
            float v = g_cand_val[b][i];
            if (v > best) { best = v; bi = (int)i; }
        }
        rv[tid] = best; ri[tid] = bi;
        __syncthreads();
        for (int s = 128; s > 0; s >>= 1) {
            if (tid < s && rv[tid + s] > rv[tid]) { rv[tid] = rv[tid + s]; ri[tid] = ri[tid + s]; }
            __syncthreads();
        }
        if (tid == 0) {
            g_topv[b * KSP + it] = rv[0];
            g_topi[b * KSP + it] = g_cand_idx[b][ri[0]];
            g_cand_val[b][ri[0]] = NEG_INF;
        }
        __syncthreads();
    }
}

// ---------------- reconstruction: deterministic gather ----------------
__global__ void output_kernel(const float* __restrict__ atoms, float* __restrict__ out) {
    __shared__ float sv[KSP];
    __shared__ int   sa[KSP];
    __shared__ int   st[KSP];
    const int b = blockIdx.y, tid = threadIdx.x;
    if (tid < KSP) {
        sv[tid] = g_topv[b * KSP + tid];
        unsigned idx = g_topi[b * KSP + tid];
        sa[tid] = (int)(idx / (unsigned)NS);
        st[tid] = (int)(idx % (unsigned)NS);
    }
    __syncthreads();
    const int p = blockIdx.x * blockDim.x + tid;
    float acc = 0.f;
#pragma unroll 8
    for (int j = 0; j < KSP; j++) {
        int o = p - st[j];
        if ((unsigned)o < (unsigned)ASZ) acc += atoms[(size_t)sa[j] * ASZ + o] * sv[j];
    }
    out[(size_t)b * NS + p] = acc;
}

// ---------------- launch ----------------
extern "C" void kernel_launch(void* const* d_in, const int* in_sizes, int n_in,
                              void* d_out, int out_size) {
    const float* orig  = (const float*)d_in[0];
    const float* atoms = (const float*)d_in[1];
    if (n_in >= 2 && in_sizes[0] == NA * ASZ) {   // defensive operand-order check
        const float* t = orig; orig = atoms; atoms = t;
    }
    float* out = (float*)d_out;

    init_kernel<<<1, 32>>>();
    corr_max_kernel<<<dim3(256, 16, NB), 256>>>(orig, atoms);
    thresh_kernel<<<NB, 256>>>();
    worklist_kernel<<<NB, 256>>>();
    recompute_kernel<<<dim3(256, NB), 256>>>(orig, atoms);
    select_kernel<<<NB, 256>>>();
    output_kernel<<<dim3(NS / 256, NB), 256>>>(atoms, out);
}

// round 6
// speedup vs baseline: 3.6643x; 3.2928x over previous
#include <cuda_runtime.h>
#include <cuda_bf16.h>
#include <cstdint>

#define NS   32768
#define NA   2048
#define ASZ  1024
#define KSP  64
#define NB   4
#define NEG_INF (-3.4e38f)
#define CAND_MAX 65536
#define NTILES   4096          // 128x128 tiles per batch: 16 atom-blocks x 256 time-blocks
#define EPS_TOTAL 1.0f         // >= 2*eps for bf16 tile-max error (est. eps ~0.2 max)

#define SIG_PAD  512
#define SIG_LEN  33792

typedef unsigned long long ull;

// ---------------- static scratch (~6.5 MB) ----------------
__device__ __align__(16) __nv_bfloat16 g_atoms_bf[(size_t)NA * ASZ];   // 4 MB
__device__ __align__(16) __nv_bfloat16 g_sig8[NB][8][SIG_LEN];         // 2.1 MB
__device__ float    g_tilemax[NB * NTILES];
__device__ float    g_thresh[NB];
__device__ unsigned g_work[NB][NTILES];
__device__ unsigned g_work_cnt[NB];
__device__ float    g_cand_val[NB][CAND_MAX];
__device__ unsigned g_cand_idx[NB][CAND_MAX];
__device__ unsigned g_cand_cnt[NB];
__device__ float    g_topv[NB * KSP];
__device__ unsigned g_topi[NB * KSP];

__device__ __forceinline__ uint32_t smem_u32(const void* p) {
    uint32_t a;
    asm("{ .reg .u64 t; cvta.to.shared.u64 t, %1; cvt.u32.u64 %0, t; }" : "=r"(a) : "l"(p));
    return a;
}

// ---------------- init / prepass ----------------
__global__ void init_kernel() {
    int i = blockIdx.x * blockDim.x + threadIdx.x;
    if (i < NB) { g_cand_cnt[i] = 0u; g_work_cnt[i] = 0u; }
}
__global__ void conv_atoms_kernel(const float* __restrict__ atoms) {
    size_t i = (size_t)blockIdx.x * blockDim.x + threadIdx.x;
    if (i < (size_t)NA * ASZ) g_atoms_bf[i] = __float2bfloat16_rn(atoms[i]);
}
__global__ void build_sig_kernel(const float* __restrict__ orig) {
    size_t i = (size_t)blockIdx.x * blockDim.x + threadIdx.x;
    if (i >= (size_t)NB * 8 * SIG_LEN) return;
    int j = (int)(i % SIG_LEN);
    int c = (int)((i / SIG_LEN) % 8);
    int b = (int)(i / ((size_t)8 * SIG_LEN));
    int s = j - SIG_PAD + c;
    g_sig8[b][c][j] = (s >= 0 && s < NS) ? __float2bfloat16_rn(orig[(size_t)b * NS + s])
                                         : __float2bfloat16_rn(0.f);
}

// ---------------- pass 1: bf16 mma.sync correlation, tile-max only ----------------
// CTA tile: 128 atoms x 128 times, K=1024 in chunks of 32. 8 warps in 4(m) x 2(n) grid,
// each warp m32 x n64 = 2 m16-frags x 8 n8-frags.
//
// Fragment-packed smem (per 32-K chunk):
//   A: [m16b(8)][k16b(2)][slot(32)][16B]  -- ldmatrix.x4 addr = blockbase + lane*16
//      slot = (row&15) | (k8half<<4)
//   B: [k16b(2)][n8b(16)][slot(16)][16B]  -- ldmatrix.x4 spans 2 adjacent n8 blocks
//      slot = (time&7) | (k8half<<3)
__global__ __launch_bounds__(256, 2)
void corr_tc_kernel() {
    __shared__ __align__(16) unsigned char sA[2][8192];
    __shared__ __align__(16) unsigned char sB[2][8192];
    __shared__ float s_wmax[8];

    const int b  = blockIdx.z;
    const int a0 = blockIdx.y << 7;
    const int t0 = blockIdx.x << 7;
    const int tid = threadIdx.x;
    const int w = tid >> 5, lane = tid & 31;
    const int wm = w & 3, wn = w >> 2;

    const uint32_t sA0 = smem_u32(sA[0]), sA1 = smem_u32(sA[1]);
    const uint32_t sB0 = smem_u32(sB[0]), sB1 = smem_u32(sB[1]);

    float acc[2][8][4];
#pragma unroll
    for (int mi = 0; mi < 2; mi++)
#pragma unroll
        for (int ni = 0; ni < 8; ni++)
#pragma unroll
            for (int r = 0; r < 4; r++) acc[mi][ni][r] = 0.f;

    auto fill = [&](int ck, int buf) {
        const int kk = ck << 5;
#pragma unroll
        for (int q = 0; q < 2; q++) {
            int i = tid + (q << 8);
            {   // A: item i -> atom row r, 8-elem k-group c8
                int r = i >> 2, c8 = i & 3;
                uint4 v = *(const uint4*)(g_atoms_bf + (size_t)(a0 + r) * ASZ + kk + (c8 << 3));
                int m16b = r >> 4, kb = c8 >> 1, h = c8 & 1;
                int slot = (r & 15) | (h << 4);
                *(uint4*)(sA[buf] + ((((m16b << 1) | kb) << 5 | slot) << 4)) = v;
            }
            {   // B: item i -> time row t, 8-elem k-group c8
                int t = i >> 2, c8 = i & 3;
                int e0 = t0 + t + kk + (c8 << 3);   // g_sig8 idx == orig idx + 512 built in
                int c = t & 7;
                uint4 v = *(const uint4*)(&g_sig8[b][c][e0 - c]);
                int n8b = t >> 3, kb = c8 >> 1, h = c8 & 1;
                int slot = (t & 7) | (h << 3);
                *(uint4*)(sB[buf] + (((kb << 4 | n8b) << 4 | slot) << 4)) = v;
            }
        }
    };

    fill(0, 0);
    __syncthreads();

    for (int ck = 0; ck < 32; ck++) {
        const int p = ck & 1;
        if (ck + 1 < 32) fill(ck + 1, p ^ 1);
        const uint32_t sAp = p ? sA1 : sA0;
        const uint32_t sBp = p ? sB1 : sB0;

#pragma unroll
        for (int kb = 0; kb < 2; kb++) {
            uint32_t a[2][4];
#pragma unroll
            for (int mi = 0; mi < 2; mi++) {
                uint32_t addr = sAp + (((((wm << 1) | mi) << 1 | kb) << 5 | lane) << 4);
                asm volatile("ldmatrix.sync.aligned.m8n8.x4.shared.b16 {%0,%1,%2,%3}, [%4];"
                    : "=r"(a[mi][0]), "=r"(a[mi][1]), "=r"(a[mi][2]), "=r"(a[mi][3]) : "r"(addr));
            }
            uint32_t bf[8][2];
#pragma unroll
            for (int jj = 0; jj < 4; jj++) {
                uint32_t addr = sBp + ((((kb << 4) | ((wn << 3) + (jj << 1))) << 4 | lane) << 4);
                asm volatile("ldmatrix.sync.aligned.m8n8.x4.shared.b16 {%0,%1,%2,%3}, [%4];"
                    : "=r"(bf[jj * 2][0]), "=r"(bf[jj * 2][1]),
                      "=r"(bf[jj * 2 + 1][0]), "=r"(bf[jj * 2 + 1][1]) : "r"(addr));
            }
#pragma unroll
            for (int mi = 0; mi < 2; mi++)
#pragma unroll
                for (int ni = 0; ni < 8; ni++)
                    asm volatile(
                        "mma.sync.aligned.m16n8k16.row.col.f32.bf16.bf16.f32 "
                        "{%0,%1,%2,%3}, {%4,%5,%6,%7}, {%8,%9}, {%0,%1,%2,%3};"
                        : "+f"(acc[mi][ni][0]), "+f"(acc[mi][ni][1]),
                          "+f"(acc[mi][ni][2]), "+f"(acc[mi][ni][3])
                        : "r"(a[mi][0]), "r"(a[mi][1]), "r"(a[mi][2]), "r"(a[mi][3]),
                          "r"(bf[ni][0]), "r"(bf[ni][1]));
        }
        __syncthreads();
    }

    // epilogue: per-thread max over 64 accs -> warp -> CTA -> g_tilemax
    float m = NEG_INF;
#pragma unroll
    for (int mi = 0; mi < 2; mi++)
#pragma unroll
        for (int ni = 0; ni < 8; ni++)
#pragma unroll
            for (int r = 0; r < 4; r++) m = fmaxf(m, acc[mi][ni][r]);
#pragma unroll
    for (int o = 16; o > 0; o >>= 1) m = fmaxf(m, __shfl_xor_sync(0xffffffffu, m, o));
    if (lane == 0) s_wmax[w] = m;
    __syncthreads();
    if (tid == 0) {
        float mm = s_wmax[0];
#pragma unroll
        for (int i = 1; i < 8; i++) mm = fmaxf(mm, s_wmax[i]);
        g_tilemax[b * NTILES + blockIdx.y * 256 + blockIdx.x] = mm;
    }
}

// ---------------- threshold: (64th-largest approx tile max) - EPS ----------------
__global__ void thresh_kernel() {
    __shared__ float sv[NTILES];
    __shared__ float rv[256];
    __shared__ int   ri[256];
    const int b = blockIdx.x, tid = threadIdx.x;
    for (int i = tid; i < NTILES; i += 256) sv[i] = g_tilemax[b * NTILES + i];
    __syncthreads();
    for (int it = 0; it < KSP; it++) {
        float best = NEG_INF; int bi = 0;
        for (int i = tid; i < NTILES; i += 256)
            if (sv[i] > best) { best = sv[i]; bi = i; }
        rv[tid] = best; ri[tid] = bi;
        __syncthreads();
        for (int s = 128; s > 0; s >>= 1) {
            if (tid < s && rv[tid + s] > rv[tid]) { rv[tid] = rv[tid + s]; ri[tid] = ri[tid + s]; }
            __syncthreads();
        }
        if (tid == 0) {
            if (it == KSP - 1) g_thresh[b] = rv[0] - EPS_TOTAL;
            sv[ri[0]] = NEG_INF;
        }
        __syncthreads();
    }
}

// ---------------- worklist: tiles whose approx max clears the threshold ----------------
__global__ void worklist_kernel() {
    const int b = blockIdx.x;
    const float tau = g_thresh[b];
    for (int i = threadIdx.x; i < NTILES; i += blockDim.x) {
        if (g_tilemax[b * NTILES + i] >= tau) {
            unsigned p = atomicAdd(&g_work_cnt[b], 1u);
            g_work[b][p] = (unsigned)i;
        }
    }
}

// ---------------- exact fp32 tile GEMM (validated R3 core, f32x2 packed) ----------------
__device__ __forceinline__ float f32x2_lo(ull v) { return __uint_as_float((unsigned)(v & 0xffffffffull)); }
__device__ __forceinline__ float f32x2_hi(ull v) { return __uint_as_float((unsigned)(v >> 32)); }

__device__ __forceinline__ void tile_gemm(
    const float* __restrict__ ob, const float* __restrict__ atoms,
    int a0, int t0, int tid, ull acc2[4][8],
    float (*As)[132], float* Bs)
{
    const int tx = tid & 15, ty = tid >> 4;
    const int kload = tid & 15, sload = tid >> 4;
#pragma unroll
    for (int i2 = 0; i2 < 4; i2++)
#pragma unroll
        for (int j = 0; j < 8; j++) acc2[i2][j] = 0ull;

    for (int kk = 0; kk < ASZ; kk += 16) {
#pragma unroll
        for (int i = 0; i < 8; i++) {
            int a = (i << 4) + sload;
            As[kload][a] = atoms[(size_t)(a0 + a) * ASZ + kk + kload];
        }
        if (tid < 160) {
            int src = t0 + kk - 512 + tid;
            Bs[tid] = (src >= 0 && src < NS) ? ob[src] : 0.f;
        }
        __syncthreads();

        unsigned br[24];
#pragma unroll
        for (int q = 0; q < 6; q++) {
            float4 v = *(const float4*)&Bs[(tx << 3) + (q << 2)];
            br[q * 4 + 0] = __float_as_uint(v.x); br[q * 4 + 1] = __float_as_uint(v.y);
            br[q * 4 + 2] = __float_as_uint(v.z); br[q * 4 + 3] = __float_as_uint(v.w);
        }
#pragma unroll
        for (int k = 0; k < 16; k++) {
            ull ar2[4];
#pragma unroll
            for (int i2 = 0; i2 < 4; i2++)
                ar2[i2] = *(const ull*)&As[k][(ty << 3) + (i2 << 1)];
#pragma unroll
            for (int j = 0; j < 8; j++) {
                ull bb;
                asm("mov.b64 %0, {%1, %1};" : "=l"(bb) : "r"(br[k + j]));
#pragma unroll
                for (int i2 = 0; i2 < 4; i2++)
                    asm("fma.rn.f32x2 %0, %1, %2, %0;"
                        : "+l"(acc2[i2][j]) : "l"(ar2[i2]), "l"(bb));
            }
        }
        __syncthreads();
    }
}

// ---------------- pass 2: exact recompute of hot tiles, compact candidates ----------------
__global__ __launch_bounds__(256, 2)
void recompute_kernel(const float* __restrict__ orig, const float* __restrict__ atoms) {
    __shared__ float As[16][132];
    __shared__ float Bs[160];
    const int b = blockIdx.y;
    const float tau = g_thresh[b];
    const unsigned cnt = g_work_cnt[b];
    const int tid = threadIdx.x;
    const int tx = tid & 15, ty = tid >> 4;

    for (unsigned w = blockIdx.x; w < cnt; w += gridDim.x) {
        unsigned tile = g_work[b][w];
        int a0 = (int)(tile >> 8) << 7;          // tile = atom_blk*256 + time_blk
        int t0 = (int)(tile & 255u) << 7;
        ull acc2[4][8];
        tile_gemm(orig + (size_t)b * NS, atoms, a0, t0, tid, acc2, As, Bs);

#pragma unroll
        for (int i2 = 0; i2 < 4; i2++) {
#pragma unroll
            for (int j = 0; j < 8; j++) {
                float vlo = f32x2_lo(acc2[i2][j]);
                float vhi = f32x2_hi(acc2[i2][j]);
                int abase = a0 + (ty << 3) + (i2 << 1);
                int t = t0 + (tx << 3) + j;
                if (vlo >= tau) {
                    unsigned pos = atomicAdd(&g_cand_cnt[b], 1u);
                    if (pos < CAND_MAX) {
                        g_cand_val[b][pos] = vlo;
                        g_cand_idx[b][pos] = (unsigned)abase * (unsigned)NS + (unsigned)t;
                    }
                }
                if (vhi >= tau) {
                    unsigned pos = atomicAdd(&g_cand_cnt[b], 1u);
                    if (pos < CAND_MAX) {
                        g_cand_val[b][pos] = vhi;
                        g_cand_idx[b][pos] = (unsigned)(abase + 1) * (unsigned)NS + (unsigned)t;
                    }
                }
            }
        }
        __syncthreads();
    }
}

// ---------------- exact top-64 among candidates ----------------
__global__ void select_kernel() {
    __shared__ float rv[256];
    __shared__ int   ri[256];
    const int b = blockIdx.x, tid = threadIdx.x;
    unsigned n = g_cand_cnt[b];
    if (n > CAND_MAX) n = CAND_MAX;
    for (int it = 0; it < KSP; it++) {
        float best = NEG_INF; int bi = 0;
        for (unsigned i = tid; i < n; i += 256) {
            float v = g_cand_val[b][i];
            if (v > best) { best = v; bi = (int)i; }
        }
        rv[tid] = best; ri[tid] = bi;
        __syncthreads();
        for (int s = 128; s > 0; s >>= 1) {
            if (tid < s && rv[tid + s] > rv[tid]) { rv[tid] = rv[tid + s]; ri[tid] = ri[tid + s]; }
            __syncthreads();
        }
        if (tid == 0) {
            g_topv[b * KSP + it] = rv[0];
            g_topi[b * KSP + it] = g_cand_idx[b][ri[0]];
            g_cand_val[b][ri[0]] = NEG_INF;
        }
        __syncthreads();
    }
}

// ---------------- reconstruction: deterministic gather ----------------
__global__ void output_kernel(const float* __restrict__ atoms, float* __restrict__ out) {
    __shared__ float sv[KSP];
    __shared__ int   sa[KSP];
    __shared__ int   st[KSP];
    const int b = blockIdx.y, tid = threadIdx.x;
    if (tid < KSP) {
        sv[tid] = g_topv[b * KSP + tid];
        unsigned idx = g_topi[b * KSP + tid];
        sa[tid] = (int)(idx / (unsigned)NS);
        st[tid] = (int)(idx % (unsigned)NS);
    }
    __syncthreads();
    const int p = blockIdx.x * blockDim.x + tid;
    float acc = 0.f;
#pragma unroll 8
    for (int j = 0; j < KSP; j++) {
        int o = p - st[j];
        if ((unsigned)o < (unsigned)ASZ) acc += atoms[(size_t)sa[j] * ASZ + o] * sv[j];
    }
    out[(size_t)b * NS + p] = acc;
}

// ---------------- launch ----------------
extern "C" void kernel_launch(void* const* d_in, const int* in_sizes, int n_in,
                              void* d_out, int out_size) {
    const float* orig  = (const float*)d_in[0];
    const float* atoms = (const float*)d_in[1];
    if (n_in >= 2 && in_sizes[0] == NA * ASZ) {   // defensive operand-order check
        const float* t = orig; orig = atoms; atoms = t;
    }
    float* out = (float*)d_out;

    init_kernel<<<1, 32>>>();
    conv_atoms_kernel<<<(NA * ASZ + 255) / 256, 256>>>(atoms);
    build_sig_kernel<<<(NB * 8 * SIG_LEN + 255) / 256, 256>>>(orig);
    corr_tc_kernel<<<dim3(256, 16, NB), 256>>>();
    thresh_kernel<<<NB, 256>>>();
    worklist_kernel<<<NB, 256>>>();
    recompute_kernel<<<dim3(256, NB), 256>>>(orig, atoms);
    select_kernel<<<NB, 256>>>();
    output_kernel<<<dim3(NS / 256, NB), 256>>>(atoms, out);
}